// round 3
// baseline (speedup 1.0000x reference)
#include <cuda_runtime.h>
#include <math.h>

// Problem constants (fixed shapes; B/N/M/NLAT derived defensively at launch)
#define LMAX 50
#define MMAX 50
#define PI_F  3.14159265358979323846f
#define TWO_PI_F 6.28318530717958647692f

// ---------------- device scratch (no allocations allowed) ----------------
__device__ float4 g_sph[4 * 4096];          // (phi, theta-pi, rho, _) per point
__device__ float  g_interp[4 * 131072];     // (B, NLAT*NLON)
__device__ float  g_ctab[1024 * MMAX];      // [NLON][MMAX] cos(2*pi*m*j/NLON)
__device__ float  g_xfT[4 * MMAX * 512];    // [b][m][k]
__device__ float  g_coeffs[4 * LMAX * MMAX];

// ---------------- stage 1: cartesian -> spherical ----------------
__global__ void prep_kernel(const float* __restrict__ pred, int BN) {
    int i = blockIdx.x * blockDim.x + threadIdx.x;
    if (i >= BN) return;
    float x = pred[3 * i + 0];
    float y = pred[3 * i + 1];
    float z = pred[3 * i + 2];
    float rho = sqrtf(x * x + y * y + z * z);
    float phi = atan2f(y, x);
    float th  = acosf(z / rho);
    g_sph[i] = make_float4(phi, th - PI_F, rho, 0.0f);
}

// ---------------- cosine table: ctab[j][m] = cos(2*pi*m*j/NLON) ----------------
__global__ void ctab_kernel(int NLON) {
    int i = blockIdx.x * blockDim.x + threadIdx.x;
    if (i >= NLON * MMAX) return;
    int j = i / MMAX;
    int m = i % MMAX;
    // 2*m*j <= 2*49*1023 < 2^24 : exact in fp32; cospif does precise pi-reduction
    g_ctab[i] = cospif((float)(2 * m * j) / (float)NLON);
}

// ---------------- stage 2: brute-force exact 3-NN + distance-weighted interp ----------------
#define KT 512   // threads per block
#define KG 4     // grid points per thread

__global__ __launch_bounds__(KT) void knn_kernel(
    const float* __restrict__ grid, int N, int M) {
    __shared__ float4 s[2048];   // all N<=2048 points of batch b
    int b  = blockIdx.y;
    int m0 = blockIdx.x * (KT * KG);
    const float4* sb = g_sph + b * N;
    for (int i = threadIdx.x; i < N; i += KT) s[i] = sb[i];
    __syncthreads();

    float gx[KG], gy[KG];
    float bd0[KG], bd1[KG], bd2[KG];   // sorted top-3 squared distances
    float br0[KG], br1[KG], br2[KG];   // matching rho (feature)
#pragma unroll
    for (int g = 0; g < KG; ++g) {
        int m = m0 + g * KT + threadIdx.x;
        float2 gc = reinterpret_cast<const float2*>(grid)[m];
        gx[g] = gc.x; gy[g] = gc.y;
        bd0[g] = bd1[g] = bd2[g] = 3.4e38f;
        br0[g] = br1[g] = br2[g] = 0.0f;
    }

#pragma unroll 4
    for (int j = 0; j < N; ++j) {
        float4 p = s[j];   // broadcast LDS.128 across warp
#pragma unroll
        for (int g = 0; g < KG; ++g) {
            float dx = p.x - gx[g];
            float dy = p.y - gy[g];
            float d  = fmaf(dy, dy, dx * dx);
            if (d < bd2[g]) {                     // rare path (~3/j)
                if (d < bd1[g]) {
                    bd2[g] = bd1[g]; br2[g] = br1[g];
                    if (d < bd0[g]) {
                        bd1[g] = bd0[g]; br1[g] = br0[g];
                        bd0[g] = d;      br0[g] = p.z;
                    } else {
                        bd1[g] = d; br1[g] = p.z;
                    }
                } else {
                    bd2[g] = d; br2[g] = p.z;
                }
            }
        }
    }

#pragma unroll
    for (int g = 0; g < KG; ++g) {
        float s0 = sqrtf(bd0[g]);
        float s1 = sqrtf(bd1[g]);
        float s2 = sqrtf(bd2[g]);
        // weights PROPORTIONAL to distance (as in the reference source)
        float v = (s0 * br0[g] + s1 * br1[g] + s2 * br2[g]) / (s0 + s1 + s2);
        g_interp[b * M + m0 + g * KT + threadIdx.x] = v;
    }
}

// ---------------- stage 3: xfT[b][m][k] = (1/NLON) * sum_j interp[b,k,j] * cos(2pi m j/NLON) ----------------
__global__ void xf_kernel(int NLAT, int NLON, int M) {
    __shared__ float srow[1024];
    int b = blockIdx.y;
    int k = blockIdx.x;                 // latitude index
    const float* src = g_interp + b * M + k * NLON;
    for (int j = threadIdx.x; j < NLON; j += blockDim.x) srow[j] = src[j];
    __syncthreads();
    int m = threadIdx.x;
    if (m < MMAX) {
        float acc = 0.0f;
        for (int j = 0; j < NLON; ++j)
            acc = fmaf(srow[j], g_ctab[j * MMAX + m], acc);   // coalesced across m
        g_xfT[(b * MMAX + m) * NLAT + k] = acc / (float)NLON;
    }
}

// ---------------- stage 4: coeffs[b,l,m] = 2*pi * sum_k xfT[b,m,k] * pct[m,l,k] ----------------
__global__ void coeff_kernel(const float* __restrict__ pct, int B, int NLAT) {
    int idx = blockIdx.x * blockDim.x + threadIdx.x;
    if (idx >= B * LMAX * MMAX) return;
    int b = idx / (LMAX * MMAX);
    int r = idx % (LMAX * MMAX);
    int l = r / MMAX;
    int m = r % MMAX;
    const float* xp = g_xfT + (b * MMAX + m) * NLAT;
    const float* pp = pct + (m * LMAX + l) * NLAT;
    float acc = 0.0f;
    for (int k = 0; k < NLAT; ++k) acc = fmaf(xp[k], pp[k], acc);
    g_coeffs[idx] = acc * TWO_PI_F;
}

// ---------------- stage 5: weighted MSE, mean over batch ----------------
__global__ void loss_kernel(const float* __restrict__ target,
                            const float* __restrict__ rect,
                            float* __restrict__ out, int B) {
    int tid = threadIdx.x;
    int total = B * LMAX * MMAX;
    float acc = 0.0f;
    for (int i = tid; i < total; i += blockDim.x) {
        int l = (i % (LMAX * MMAX)) / MMAX;
        float d = g_coeffs[i] - target[i];
        acc += d * d * rect[l];
    }
    __shared__ float sm[32];
#pragma unroll
    for (int o = 16; o > 0; o >>= 1) acc += __shfl_down_sync(0xffffffffu, acc, o);
    if ((tid & 31) == 0) sm[tid >> 5] = acc;
    __syncthreads();
    if (tid < 32) {
        float v = (tid < (blockDim.x >> 5)) ? sm[tid] : 0.0f;
#pragma unroll
        for (int o = 16; o > 0; o >>= 1) v += __shfl_down_sync(0xffffffffu, v, o);
        if (tid == 0) out[0] = v / (float)B;
    }
}

// ---------------- launch ----------------
extern "C" void kernel_launch(void* const* d_in, const int* in_sizes, int n_in,
                              void* d_out, int out_size) {
    const float* pred   = (const float*)d_in[0];
    const float* target = (const float*)d_in[1];
    const float* grid   = (const float*)d_in[2];
    const float* pct    = (const float*)d_in[3];
    const float* rect   = (const float*)d_in[4];

    int B    = in_sizes[1] / (LMAX * MMAX);      // 2
    int N    = in_sizes[0] / (3 * B);            // 2048
    int M    = in_sizes[2] / 2;                  // 131072
    int NLAT = in_sizes[3] / (LMAX * MMAX);      // 256
    int NLON = M / NLAT;                         // 512
    int BN   = B * N;

    prep_kernel<<<(BN + 255) / 256, 256>>>(pred, BN);
    ctab_kernel<<<(NLON * MMAX + 255) / 256, 256>>>(NLON);

    dim3 kgrid(M / (KT * KG), B);                // 64 x 2 = 128 CTAs
    knn_kernel<<<kgrid, KT>>>(grid, N, M);

    xf_kernel<<<dim3(NLAT, B), 64>>>(NLAT, NLON, M);
    coeff_kernel<<<(B * LMAX * MMAX + 255) / 256, 256>>>(pct, B, NLAT);
    loss_kernel<<<1, 256>>>(target, rect, (float*)d_out, B);
}

// round 6
// speedup vs baseline: 1.5652x; 1.5652x over previous
#include <cuda_runtime.h>
#include <math.h>

// Problem constants (fixed shapes; derived defensively at launch)
#define LMAX 50
#define MMAX 50
#define PI_F  3.14159265358979323846f
#define TWO_PI_F 6.28318530717958647692f
#define NP 2048          // padded point count for sort/KNN

// ---------------- device scratch (no allocations allowed) ----------------
__device__ float  g_ys[4 * NP];             // sorted y per batch
__device__ float  g_xs[4 * NP];             // matching x (phi)
__device__ float  g_rs[4 * NP];             // matching rho
__device__ float  g_interp[4 * 131072];     // (B, NLAT*NLON)
__device__ float  g_ctab[1024 * MMAX];      // [NLON][MMAX] cos(2*pi*m*j/NLON)
__device__ float  g_xfT[4 * MMAX * 512];    // [b][m][k]
__device__ float  g_coeffs[4 * LMAX * MMAX];

// ---------------- cosine table: ctab[j][m] = cos(2*pi*m*j/NLON) ----------------
__global__ void ctab_kernel(int NLON) {
    int i = blockIdx.x * blockDim.x + threadIdx.x;
    if (i >= NLON * MMAX) return;
    int j = i / MMAX;
    int m = i % MMAX;
    // 2*m*j < 2^24 : exact fp32; cospif does precise pi-reduction
    g_ctab[i] = cospif((float)(2 * m * j) / (float)NLON);
}

// ---------------- stage 1: cart->sph fused with bitonic sort by y, per batch ----------------
__global__ __launch_bounds__(1024) void prep_sort_kernel(
    const float* __restrict__ pred, int N) {
    __shared__ float key[NP];      // y = theta - pi (sort key)
    __shared__ int   sidx[NP];
    __shared__ float sx[NP];       // phi
    __shared__ float sr[NP];       // rho
    int b = blockIdx.x;
    int tid = threadIdx.x;
    for (int i = tid; i < NP; i += 1024) {
        if (i < N) {
            float x = pred[3 * (b * N + i) + 0];
            float y = pred[3 * (b * N + i) + 1];
            float z = pred[3 * (b * N + i) + 2];
            float rho = sqrtf(x * x + y * y + z * z);
            key[i] = acosf(z / rho) - PI_F;
            sx[i]  = atan2f(y, x);
            sr[i]  = rho;
        } else {
            key[i] = 1e30f;        // pad high
            sx[i]  = 0.0f;
            sr[i]  = 0.0f;
        }
        sidx[i] = i;
    }
    __syncthreads();
    for (int k = 2; k <= NP; k <<= 1) {
        for (int jj = k >> 1; jj > 0; jj >>= 1) {
            int i = ((tid & ~(jj - 1)) << 1) | (tid & (jj - 1));
            int p = i | jj;
            bool up = ((i & k) == 0);
            float ki = key[i], kp = key[p];
            if ((ki > kp) == up) {
                key[i] = kp; key[p] = ki;
                int t = sidx[i]; sidx[i] = sidx[p]; sidx[p] = t;
            }
            __syncthreads();
        }
    }
    for (int i = tid; i < NP; i += 1024) {
        int si = sidx[i];
        g_ys[b * NP + i] = key[i];
        g_xs[b * NP + i] = sx[si];
        g_rs[b * NP + i] = sr[si];
    }
}

// ---------------- stage 2: exact 3-NN via sorted-y band walk ----------------
// Thread owns one phi-column (g1) and KG=4 theta-rows (same g1, different g0).
// Walk candidates outward from g1 in sorted-y order; Delta_y^2 is an exact
// lower bound on d^2, monotone along the walk -> provably exact early exit.
// All distance arithmetic uses explicit rn mul/add to match the reference's
// rounding (round(dx^2) + round(dy^2)) exactly -- no FMA contraction.
#define KG 4

__global__ __launch_bounds__(512) void knn2_kernel(
    const float* __restrict__ grid, int M, int NLON, int NROW) {
    __shared__ float ys[NP], xs[NP], rs[NP];
    int b = blockIdx.y;
    int rg = blockIdx.x;            // row group 0..NROW/KG-1
    int c = threadIdx.x;            // column (phi index), blockDim == NLON
    for (int i = threadIdx.x; i < NP; i += blockDim.x) {
        ys[i] = g_ys[b * NP + i];
        xs[i] = g_xs[b * NP + i];
        rs[i] = g_rs[b * NP + i];
    }
    __syncthreads();

    int rowspan = NROW / KG;
    int m0 = rg * NLON + c;
    float g1 = grid[2 * m0 + 1];
    float g0k[KG];
#pragma unroll
    for (int k = 0; k < KG; ++k)
        g0k[k] = grid[2 * (m0 + k * rowspan * NLON)];

    float bd0[KG], bd1[KG], bd2[KG];
    float br0[KG], br1[KG], br2[KG];
#pragma unroll
    for (int k = 0; k < KG; ++k) {
        bd0[k] = bd1[k] = bd2[k] = 3.4e38f;
        br0[k] = br1[k] = br2[k] = 0.0f;
    }
    float bw = 3.4e38f;   // max over k of bd2[k]

    // lower_bound(g1) in sorted ys
    int lo2 = 0, hi2 = NP;
    while (lo2 < hi2) {
        int mid = (lo2 + hi2) >> 1;
        if (ys[mid] < g1) lo2 = mid + 1; else hi2 = mid;
    }
    int lo = lo2 - 1, hi = lo2;
    float ylo = (lo >= 0) ? ys[lo] : -3e38f;
    float yhi = (hi < NP) ? ys[hi] :  3e38f;

    while (true) {
        float dlo = g1 - ylo;       // >= 0
        float dhi = yhi - g1;       // >= 0
        bool tl = dlo <= dhi;
        float t = tl ? dlo : dhi;
        float dyy = __fmul_rn(t, t);     // matches reference round(dy^2)
        if (dyy >= bw) break;            // exact exit (also fires on exhaust)
        int j;
        if (tl) { j = lo; --lo; ylo = (lo >= 0) ? ys[lo] : -3e38f; }
        else    { j = hi; ++hi; yhi = (hi < NP) ? ys[hi] :  3e38f; }
        float xj = xs[j];
        float rj = rs[j];
#pragma unroll
        for (int k = 0; k < KG; ++k) {
            float dx = xj - g0k[k];
            float d  = __fadd_rn(__fmul_rn(dx, dx), dyy);  // round(dx^2)+round(dy^2)
            if (d < bd2[k]) {
                if (d < bd1[k]) {
                    bd2[k] = bd1[k]; br2[k] = br1[k];
                    if (d < bd0[k]) {
                        bd1[k] = bd0[k]; br1[k] = br0[k];
                        bd0[k] = d;      br0[k] = rj;
                    } else {
                        bd1[k] = d; br1[k] = rj;
                    }
                } else {
                    bd2[k] = d; br2[k] = rj;
                }
                bw = fmaxf(fmaxf(bd2[0], bd2[1]), fmaxf(bd2[2], bd2[3]));
            }
        }
    }

#pragma unroll
    for (int k = 0; k < KG; ++k) {
        float s0 = sqrtf(bd0[k]);
        float s1 = sqrtf(bd1[k]);
        float s2 = sqrtf(bd2[k]);
        // weights PROPORTIONAL to distance (as in reference source)
        float v = (s0 * br0[k] + s1 * br1[k] + s2 * br2[k]) / (s0 + s1 + s2);
        g_interp[b * M + m0 + k * rowspan * NLON] = v;
    }
}

// ---------------- stage 3: xfT[b][m][k] = (1/NLON) * sum_j interp[bk][j]*ctab[j][m] ----------------
#define XF_TK 8
__global__ __launch_bounds__(XF_TK * MMAX) void xf2_kernel(int NLAT, int NLON) {
    __shared__ float si[XF_TK][512];
    int bk0 = blockIdx.x * XF_TK;
    int tid = threadIdx.x;
    for (int idx = tid; idx < XF_TK * NLON; idx += blockDim.x)
        si[idx / 512][idx % 512] = g_interp[bk0 * NLON + idx];
    __syncthreads();
    int r = tid / MMAX;             // row within tile
    int m = tid % MMAX;
    float a0 = 0.f, a1 = 0.f, a2 = 0.f, a3 = 0.f;
    const float* cp = g_ctab + m;
    const float* srow = si[r];
    for (int j = 0; j < NLON; j += 4) {
        a0 = fmaf(srow[j + 0], cp[(j + 0) * MMAX], a0);
        a1 = fmaf(srow[j + 1], cp[(j + 1) * MMAX], a1);
        a2 = fmaf(srow[j + 2], cp[(j + 2) * MMAX], a2);
        a3 = fmaf(srow[j + 3], cp[(j + 3) * MMAX], a3);
    }
    float acc = (a0 + a1) + (a2 + a3);
    int bk = bk0 + r;
    int b = bk / NLAT;
    int k = bk % NLAT;
    g_xfT[(b * MMAX + m) * NLAT + k] = acc / (float)NLON;
}

// ---------------- stage 4: coeffs[b,l,m] = 2*pi * sum_k xfT[b,m,k] * pct[m,l,k] ----------------
__global__ void coeff_kernel(const float* __restrict__ pct, int B, int NLAT) {
    int idx = blockIdx.x * blockDim.x + threadIdx.x;
    if (idx >= B * LMAX * MMAX) return;
    int b = idx / (LMAX * MMAX);
    int r = idx % (LMAX * MMAX);
    int l = r / MMAX;
    int m = r % MMAX;
    const float* xp = g_xfT + (b * MMAX + m) * NLAT;
    const float* pp = pct + (m * LMAX + l) * NLAT;
    float a0 = 0.f, a1 = 0.f, a2 = 0.f, a3 = 0.f;
    for (int k = 0; k < NLAT; k += 4) {
        a0 = fmaf(xp[k + 0], pp[k + 0], a0);
        a1 = fmaf(xp[k + 1], pp[k + 1], a1);
        a2 = fmaf(xp[k + 2], pp[k + 2], a2);
        a3 = fmaf(xp[k + 3], pp[k + 3], a3);
    }
    g_coeffs[idx] = ((a0 + a1) + (a2 + a3)) * TWO_PI_F;
}

// ---------------- stage 5: weighted MSE, mean over batch ----------------
__global__ void loss_kernel(const float* __restrict__ target,
                            const float* __restrict__ rect,
                            float* __restrict__ out, int B) {
    int tid = threadIdx.x;
    int total = B * LMAX * MMAX;
    float acc = 0.0f;
    for (int i = tid; i < total; i += blockDim.x) {
        int l = (i % (LMAX * MMAX)) / MMAX;
        float d = g_coeffs[i] - target[i];
        acc += d * d * rect[l];
    }
    __shared__ float sm[32];
#pragma unroll
    for (int o = 16; o > 0; o >>= 1) acc += __shfl_down_sync(0xffffffffu, acc, o);
    if ((tid & 31) == 0) sm[tid >> 5] = acc;
    __syncthreads();
    if (tid < 32) {
        float v = (tid < (blockDim.x >> 5)) ? sm[tid] : 0.0f;
#pragma unroll
        for (int o = 16; o > 0; o >>= 1) v += __shfl_down_sync(0xffffffffu, v, o);
        if (tid == 0) out[0] = v / (float)B;
    }
}

// ---------------- launch ----------------
extern "C" void kernel_launch(void* const* d_in, const int* in_sizes, int n_in,
                              void* d_out, int out_size) {
    const float* pred   = (const float*)d_in[0];
    const float* target = (const float*)d_in[1];
    const float* grid   = (const float*)d_in[2];
    const float* pct    = (const float*)d_in[3];
    const float* rect   = (const float*)d_in[4];

    int B    = in_sizes[1] / (LMAX * MMAX);      // 2
    int N    = in_sizes[0] / (3 * B);            // 2048
    int M    = in_sizes[2] / 2;                  // 131072
    int NLAT = in_sizes[3] / (LMAX * MMAX);      // 256
    int NLON = M / NLAT;                         // 512

    ctab_kernel<<<(NLON * MMAX + 255) / 256, 256>>>(NLON);
    prep_sort_kernel<<<B, 1024>>>(pred, N);

    dim3 kgrid(NLAT / KG, B);                    // 64 x 2
    knn2_kernel<<<kgrid, NLON>>>(grid, M, NLON, NLAT);

    xf2_kernel<<<(B * NLAT) / XF_TK, XF_TK * MMAX>>>(NLAT, NLON);
    coeff_kernel<<<(B * LMAX * MMAX + 255) / 256, 256>>>(pct, B, NLAT);
    loss_kernel<<<1, 256>>>(target, rect, (float*)d_out, B);
}

// round 9
// speedup vs baseline: 2.5161x; 1.6075x over previous
#include <cuda_runtime.h>
#include <math.h>

// Problem constants (fixed shapes; derived defensively at launch)
#define LMAX 50
#define MMAX 50
#define PI_F  3.14159265358979323846f
#define TWO_PI_F 6.28318530717958647692f
#define NP 2048          // padded point count for sort/KNN

// ---------------- device scratch (no allocations allowed) ----------------
__device__ float  g_ys[4 * NP];             // sorted y per batch
__device__ float  g_xs[4 * NP];             // matching x (phi)
__device__ float  g_rs[4 * NP];             // matching rho
__device__ float  g_interp[4 * 131072];     // (B, NLAT*NLON)
__device__ float  g_ctabT[MMAX * 1024];     // [m][j] cos(2*pi*m*j/NLON)
__device__ float  g_xfT[4 * MMAX * 512];    // [b][m][k]

// ---------------- zero the scalar output ----------------
__global__ void zero_kernel(float* out) { out[0] = 0.0f; }

// ---------------- cosine table (transposed): ctabT[m][j] = cos(2*pi*m*j/NLON) ----------------
__global__ void ctabT_kernel(int NLON) {
    int i = blockIdx.x * blockDim.x + threadIdx.x;
    if (i >= NLON * MMAX) return;
    int m = i / NLON;
    int j = i % NLON;
    // 2*m*j < 2^24 : exact fp32; cospif does precise pi-reduction
    g_ctabT[m * NLON + j] = cospif((float)(2 * m * j) / (float)NLON);
}

// ---------------- stage 1: cart->sph fused with bitonic sort by y, per batch ----------------
__global__ __launch_bounds__(1024) void prep_sort_kernel(
    const float* __restrict__ pred, int N) {
    __shared__ float key[NP];      // y = theta - pi (sort key)
    __shared__ int   sidx[NP];
    __shared__ float sx[NP];       // phi
    __shared__ float sr[NP];       // rho
    int b = blockIdx.x;
    int tid = threadIdx.x;
    for (int i = tid; i < NP; i += 1024) {
        if (i < N) {
            float x = pred[3 * (b * N + i) + 0];
            float y = pred[3 * (b * N + i) + 1];
            float z = pred[3 * (b * N + i) + 2];
            float rho = sqrtf(x * x + y * y + z * z);
            key[i] = acosf(z / rho) - PI_F;
            sx[i]  = atan2f(y, x);
            sr[i]  = rho;
        } else {
            key[i] = 1e30f;        // pad high
            sx[i]  = 0.0f;
            sr[i]  = 0.0f;
        }
        sidx[i] = i;
    }
    __syncthreads();
    for (int k = 2; k <= NP; k <<= 1) {
        for (int jj = k >> 1; jj > 0; jj >>= 1) {
            int i = ((tid & ~(jj - 1)) << 1) | (tid & (jj - 1));
            int p = i | jj;
            bool up = ((i & k) == 0);
            float ki = key[i], kp = key[p];
            if ((ki > kp) == up) {
                key[i] = kp; key[p] = ki;
                int t = sidx[i]; sidx[i] = sidx[p]; sidx[p] = t;
            }
            __syncthreads();
        }
    }
    for (int i = tid; i < NP; i += 1024) {
        int si = sidx[i];
        g_ys[b * NP + i] = key[i];
        g_xs[b * NP + i] = sx[si];
        g_rs[b * NP + i] = sr[si];
    }
}

// ---------------- stage 2: exact 3-NN via sorted-y band walk ----------------
// Thread owns one phi-column (g1) and KG=4 theta-rows (same g1, different g0).
// Walk candidates outward from g1 in sorted-y order; Delta_y^2 is an exact
// lower bound on d^2, monotone along the walk -> provably exact early exit.
// Distance arithmetic uses explicit rn mul/add to match reference rounding
// (round(dx^2) + round(dy^2)) exactly -- no FMA contraction.
#define KG 4
#define KNT 256

__global__ __launch_bounds__(KNT) void knn2_kernel(
    const float* __restrict__ grid, int M, int NLON, int NROW) {
    __shared__ float ys[NP], xs[NP], rs[NP];
    int b  = blockIdx.z;
    int rg = blockIdx.y;                      // row group 0..NROW/KG-1
    int c  = blockIdx.x * KNT + threadIdx.x;  // column (index along dim-1)
    for (int i = threadIdx.x; i < NP; i += KNT) {
        ys[i] = g_ys[b * NP + i];
        xs[i] = g_xs[b * NP + i];
        rs[i] = g_rs[b * NP + i];
    }
    __syncthreads();

    int rowspan = NROW / KG;
    int m0 = rg * NLON + c;
    float g1 = grid[2 * m0 + 1];
    float g0k[KG];
#pragma unroll
    for (int k = 0; k < KG; ++k)
        g0k[k] = grid[2 * (m0 + k * rowspan * NLON)];

    float bd0[KG], bd1[KG], bd2[KG];
    float br0[KG], br1[KG], br2[KG];
#pragma unroll
    for (int k = 0; k < KG; ++k) {
        bd0[k] = bd1[k] = bd2[k] = 3.4e38f;
        br0[k] = br1[k] = br2[k] = 0.0f;
    }
    float bw = 3.4e38f;   // max over k of bd2[k]

    // lower_bound(g1) in sorted ys
    int lo2 = 0, hi2 = NP;
    while (lo2 < hi2) {
        int mid = (lo2 + hi2) >> 1;
        if (ys[mid] < g1) lo2 = mid + 1; else hi2 = mid;
    }
    int lo = lo2 - 1, hi = lo2;
    // software pipeline: current y + one-ahead y per side (hides LDS latency)
    float ylo  = (lo >= 0)     ? ys[lo]     : -3e38f;
    float yhi  = (hi < NP)     ? ys[hi]     :  3e38f;
    float ylo2 = (lo - 1 >= 0) ? ys[lo - 1] : -3e38f;
    float yhi2 = (hi + 1 < NP) ? ys[hi + 1] :  3e38f;

    while (true) {
        float dlo = g1 - ylo;       // >= 0
        float dhi = yhi - g1;       // >= 0
        bool tl = dlo <= dhi;
        float t = tl ? dlo : dhi;
        float dyy = __fmul_rn(t, t);     // matches reference round(dy^2)
        if (dyy >= bw) break;            // exact exit (also fires on exhaust)
        int j;
        if (tl) {
            j = lo; --lo;
            ylo = ylo2;
            ylo2 = (lo - 1 >= 0) ? ys[lo - 1] : -3e38f;
        } else {
            j = hi; ++hi;
            yhi = yhi2;
            yhi2 = (hi + 1 < NP) ? ys[hi + 1] : 3e38f;
        }
        float xj = xs[j];
        float rj = rs[j];
#pragma unroll
        for (int k = 0; k < KG; ++k) {
            float dx = xj - g0k[k];
            float d  = __fadd_rn(__fmul_rn(dx, dx), dyy);  // round(dx^2)+round(dy^2)
            if (d < bd2[k]) {
                if (d < bd1[k]) {
                    bd2[k] = bd1[k]; br2[k] = br1[k];
                    if (d < bd0[k]) {
                        bd1[k] = bd0[k]; br1[k] = br0[k];
                        bd0[k] = d;      br0[k] = rj;
                    } else {
                        bd1[k] = d; br1[k] = rj;
                    }
                } else {
                    bd2[k] = d; br2[k] = rj;
                }
                bw = fmaxf(fmaxf(bd2[0], bd2[1]), fmaxf(bd2[2], bd2[3]));
            }
        }
    }

#pragma unroll
    for (int k = 0; k < KG; ++k) {
        float s0 = sqrtf(bd0[k]);
        float s1 = sqrtf(bd1[k]);
        float s2 = sqrtf(bd2[k]);
        // weights PROPORTIONAL to distance (as in reference source)
        float v = (s0 * br0[k] + s1 * br1[k] + s2 * br2[k]) / (s0 + s1 + s2);
        g_interp[b * M + m0 + k * rowspan * NLON] = v;
    }
}

// ---------------- stage 3: warp-per-(row,m) dot products ----------------
// xfT[b][m][k] = (1/NLON) * sum_j interp[bk][j] * ctabT[m][j]
__global__ __launch_bounds__(256) void xf3_kernel(int NLAT, int NLON) {
    __shared__ float srow[1024];
    int bk = blockIdx.x;
    int b = bk / NLAT;
    int k = bk % NLAT;
    for (int j = threadIdx.x; j < NLON; j += 256)
        srow[j] = g_interp[bk * NLON + j];
    __syncthreads();
    int w    = threadIdx.x >> 5;
    int lane = threadIdx.x & 31;
    float inv = 1.0f / (float)NLON;
    for (int m = w; m < MMAX; m += 8) {
        const float* ct = g_ctabT + m * NLON;
        float acc = 0.0f;
        for (int j = lane; j < NLON; j += 32)
            acc = fmaf(srow[j], ct[j], acc);        // conflict-free LDS + coalesced LDG
#pragma unroll
        for (int o = 16; o > 0; o >>= 1)
            acc += __shfl_down_sync(0xffffffffu, acc, o);
        if (lane == 0)
            g_xfT[(b * MMAX + m) * NLAT + k] = acc * inv;
    }
}

// ---------------- stage 4+5 fused: coeff + weighted MSE ----------------
// warp-per-output: coeff = 2*pi * sum_k xfT[b,m,k]*pct[m,l,k];
// each block atomically adds its partial loss into out[0].
__global__ __launch_bounds__(256) void coeff_loss_kernel(
    const float* __restrict__ pct, const float* __restrict__ target,
    const float* __restrict__ rect, float* __restrict__ out,
    int B, int NLAT) {
    __shared__ float sm[8];
    if (threadIdx.x < 8) sm[threadIdx.x] = 0.0f;
    __syncthreads();
    int w    = blockIdx.x * 8 + (threadIdx.x >> 5);
    int lane = threadIdx.x & 31;
    if (w < B * LMAX * MMAX) {
        int b = w / (LMAX * MMAX);
        int r = w % (LMAX * MMAX);
        int l = r / MMAX;
        int m = r % MMAX;
        const float* xp = g_xfT + (b * MMAX + m) * NLAT;
        const float* pp = pct + (m * LMAX + l) * NLAT;
        float acc = 0.0f;
        for (int k = lane; k < NLAT; k += 32)
            acc = fmaf(xp[k], pp[k], acc);
#pragma unroll
        for (int o = 16; o > 0; o >>= 1)
            acc += __shfl_down_sync(0xffffffffu, acc, o);
        if (lane == 0) {
            float cf = acc * TWO_PI_F;
            float d = cf - target[w];
            sm[threadIdx.x >> 5] = d * d * rect[l] / (float)B;
        }
    }
    __syncthreads();
    if (threadIdx.x == 0) {
        float s = (sm[0] + sm[1]) + (sm[2] + sm[3])
                + (sm[4] + sm[5]) + (sm[6] + sm[7]);
        atomicAdd(out, s);
    }
}

// ---------------- launch ----------------
extern "C" void kernel_launch(void* const* d_in, const int* in_sizes, int n_in,
                              void* d_out, int out_size) {
    const float* pred   = (const float*)d_in[0];
    const float* target = (const float*)d_in[1];
    const float* grid   = (const float*)d_in[2];
    const float* pct    = (const float*)d_in[3];
    const float* rect   = (const float*)d_in[4];

    int B    = in_sizes[1] / (LMAX * MMAX);      // 2
    int N    = in_sizes[0] / (3 * B);            // 2048
    int M    = in_sizes[2] / 2;                  // 131072
    int NLAT = in_sizes[3] / (LMAX * MMAX);      // 256
    int NLON = M / NLAT;                         // 512

    zero_kernel<<<1, 1>>>((float*)d_out);                          // launch 1
    ctabT_kernel<<<(NLON * MMAX + 255) / 256, 256>>>(NLON);        // launch 2
    prep_sort_kernel<<<B, 1024>>>(pred, N);                        // launch 3

    dim3 kgrid(NLON / KNT, NLAT / KG, B);                          // 2 x 64 x 2
    knn2_kernel<<<kgrid, KNT>>>(grid, M, NLON, NLAT);              // launch 4

    xf3_kernel<<<B * NLAT, 256>>>(NLAT, NLON);                     // launch 5

    int nout = B * LMAX * MMAX;
    coeff_loss_kernel<<<(nout + 7) / 8, 256>>>(pct, target, rect,
                                               (float*)d_out, B, NLAT); // launch 6
}